// round 11
// baseline (speedup 1.0000x reference)
#include <cuda_runtime.h>
#include <cuda_bf16.h>
#include <cstdint>

#define N_PTS 384
#define DIM 128
#define ROWF 132              // padded floats per row (33 float4)
#define MARGIN 0.3f
#define GRID_B 96
#define BLK 384
#define ANCH 4
#define NWARP 12

// smem carve (bytes)
#define SM_E_BYTES (N_PTS * ROWF * 4)                 // 202752
#define SM_POS_OFF SM_E_BYTES
#define SM_NEG_OFF (SM_POS_OFF + ANCH * N_PTS * 4)    // +6144
#define SM_CNT_OFF (SM_NEG_OFF + ANCH * N_PTS * 4)    // +6144
#define SM_NRM_OFF (SM_CNT_OFF + ANCH * 2 * 4)        // +32
#define SM_WL_OFF  (SM_NRM_OFF + ANCH * 4)            // +16
#define SM_WC_OFF  (SM_WL_OFF + NWARP * 4)            // +48
#define SM_TOTAL   (SM_WC_OFF + NWARP * 4)            // ~215.2 KB

// Accumulators: reset by the last-ticket block each run (graph-replay safe).
__device__ float g_acc[2];
__device__ unsigned int g_ticket;

__global__ __launch_bounds__(BLK, 1) void fused_triplet(
    const float* __restrict__ E,
    const int* __restrict__ labels,
    float* __restrict__ out, int out_size) {

    extern __shared__ char smem[];
    float4* sE4 = reinterpret_cast<float4*>(smem);
    float (*spos)[N_PTS] = reinterpret_cast<float(*)[N_PTS]>(smem + SM_POS_OFF);
    float (*sneg)[N_PTS] = reinterpret_cast<float(*)[N_PTS]>(smem + SM_NEG_OFF);
    int (*cnts)[2] = reinterpret_cast<int(*)[2]>(smem + SM_CNT_OFF);
    float* snrm = reinterpret_cast<float*>(smem + SM_NRM_OFF);
    float* wl = reinterpret_cast<float*>(smem + SM_WL_OFF);
    float* wc = reinterpret_cast<float*>(smem + SM_WC_OFF);

    const int t = threadIdx.x;
    const int lane = t & 31;
    const int warp = t >> 5;
    const int a0 = blockIdx.x * ANCH;

    if (t < ANCH * 2) ((int*)cnts)[t] = 0;

    // ---- Stage full E into smem (coalesced; per-warp one row per pass) ----
    const float4* E4g = reinterpret_cast<const float4*>(E);
#pragma unroll
    for (int v = t; v < N_PTS * 32; v += BLK) {
        int r = v >> 5;
        int c4 = v & 31;
        sE4[r * 33 + c4] = E4g[v];
    }

    const int lab_t = __ldg(&labels[t]);
    int lab_a[ANCH];
#pragma unroll
    for (int a = 0; a < ANCH; a++) lab_a[a] = __ldg(&labels[a0 + a]);

    __syncthreads();

    // ---- Gram dots: column j = t vs the 4 anchors, plus self-norm ----
    const float4* erow = sE4 + t * 33;
    const float4* ar0 = sE4 + (a0 + 0) * 33;
    const float4* ar1 = sE4 + (a0 + 1) * 33;
    const float4* ar2 = sE4 + (a0 + 2) * 33;
    const float4* ar3 = sE4 + (a0 + 3) * 33;

    float acc0 = 0.f, acc1 = 0.f, acc2 = 0.f, acc3 = 0.f, accn = 0.f;
#pragma unroll 8
    for (int k4 = 0; k4 < 32; k4++) {
        float4 e = erow[k4];
        float4 v0 = ar0[k4];
        float4 v1 = ar1[k4];
        float4 v2 = ar2[k4];
        float4 v3 = ar3[k4];
        accn = fmaf(e.x, e.x, accn);
        accn = fmaf(e.y, e.y, accn);
        accn = fmaf(e.z, e.z, accn);
        accn = fmaf(e.w, e.w, accn);
        acc0 = fmaf(e.x, v0.x, acc0);
        acc0 = fmaf(e.y, v0.y, acc0);
        acc0 = fmaf(e.z, v0.z, acc0);
        acc0 = fmaf(e.w, v0.w, acc0);
        acc1 = fmaf(e.x, v1.x, acc1);
        acc1 = fmaf(e.y, v1.y, acc1);
        acc1 = fmaf(e.z, v1.z, acc1);
        acc1 = fmaf(e.w, v1.w, acc1);
        acc2 = fmaf(e.x, v2.x, acc2);
        acc2 = fmaf(e.y, v2.y, acc2);
        acc2 = fmaf(e.z, v2.z, acc2);
        acc2 = fmaf(e.w, v2.w, acc2);
        acc3 = fmaf(e.x, v3.x, acc3);
        acc3 = fmaf(e.y, v3.y, acc3);
        acc3 = fmaf(e.z, v3.z, acc3);
        acc3 = fmaf(e.w, v3.w, acc3);
    }

    // Publish anchor norms (threads whose column IS an anchor).
    if (t >= a0 && t < a0 + ANCH) snrm[t - a0] = accn;
    __syncthreads();

    // ---- Compaction per anchor (ballot-aggregated) ----
    const unsigned ltm = (1u << lane) - 1u;
    float gv[ANCH] = {acc0, acc1, acc2, acc3};
#pragma unroll
    for (int a = 0; a < ANCH; a++) {
        const float dj = snrm[a] + accn - 2.f * gv[a];   // dist(anchor, t)
        const bool same = (lab_t == lab_a[a]);

        unsigned ms = __ballot_sync(0xFFFFFFFFu, same);
        unsigned md = ~ms;

        int bp = 0, bn = 0;
        if (lane == 0) {
            bp = atomicAdd(&cnts[a][0], __popc(ms));
            bn = atomicAdd(&cnts[a][1], __popc(md));
        }
        bp = __shfl_sync(0xFFFFFFFFu, bp, 0);
        bn = __shfl_sync(0xFFFFFFFFu, bn, 0);

        if (same) spos[a][bp + __popc(ms & ltm)] = dj;
        else      sneg[a][bn + __popc(md & ltm)] = dj;
    }
    __syncthreads();

    // ---- Pair loops: thread holds its negative, iterates positives ----
    float loss = 0.f, cnt = 0.f;
#pragma unroll
    for (int a = 0; a < ANCH; a++) {
        const int P = cnts[a][0];
        const int M = cnts[a][1];
        if (t < M) {
            const float dnm = sneg[a][t] - MARGIN;
            for (int p = 0; p < P; p++) {
                float L = spos[a][p] - dnm;
                if (L > 0.f && L < MARGIN) { loss += L; cnt += 1.f; }
            }
        }
    }

    // ---- Reduce + global accumulate + last-block writeout ----
#pragma unroll
    for (int off = 16; off > 0; off >>= 1) {
        loss += __shfl_down_sync(0xFFFFFFFFu, loss, off);
        cnt  += __shfl_down_sync(0xFFFFFFFFu, cnt,  off);
    }
    if (lane == 0) { wl[warp] = loss; wc[warp] = cnt; }
    __syncthreads();

    if (t == 0) {
        float l = 0.f, c = 0.f;
#pragma unroll
        for (int w = 0; w < NWARP; w++) { l += wl[w]; c += wc[w]; }
        atomicAdd(&g_acc[0], l);
        atomicAdd(&g_acc[1], c);
        __threadfence();
        unsigned int done = atomicAdd(&g_ticket, 1u);
        if ((done % GRID_B) == GRID_B - 1) {
            __threadfence();
            out[0] = g_acc[0];
            out[1] = g_acc[1];
            for (int k = 2; k < out_size; k++) out[k] = 0.f;
            g_acc[0] = 0.f;
            g_acc[1] = 0.f;
        }
    }
}

extern "C" void kernel_launch(void* const* d_in, const int* in_sizes, int n_in,
                              void* d_out, int out_size) {
    const float* embeddings = (const float*)d_in[0];
    const int* labels = (const int*)d_in[1];
    float* out = (float*)d_out;

    // Opt in to >48KB dynamic smem (pure function-attribute state, not a
    // stream op; idempotent and capture-safe).
    cudaFuncSetAttribute(fused_triplet,
                         cudaFuncAttributeMaxDynamicSharedMemorySize, SM_TOTAL);

    fused_triplet<<<GRID_B, BLK, SM_TOTAL>>>(embeddings, labels, out, out_size);
}

// round 14
// speedup vs baseline: 1.2959x; 1.2959x over previous
#include <cuda_runtime.h>
#include <cuda_bf16.h>
#include <cstdint>

#define N_PTS 384
#define DIM 128
#define MARGIN 0.3f
#define PROD_B 144              // 12x12 gram tiles
#define CONS_B 128              // 3 anchors each
#define GRID_B (PROD_B + CONS_B)
#define BLK 384
#define NWARP 12
#define ANCH 3

// Scratch (no allocations allowed).
__device__ float g_gram[N_PTS * N_PTS];
__device__ float g_nrm[N_PTS];

// Flags / accumulators. g_grp, g_nrmc, g_acc reset by last-ticket consumer;
// g_ticket uses modulo-generation and is never reset.
__device__ unsigned int g_grp[12];
__device__ unsigned int g_nrmc;
__device__ float g_acc[2];
__device__ unsigned int g_ticket;

__global__ __launch_bounds__(BLK) void triplet_one(
    const float* __restrict__ E,
    const int* __restrict__ labels,
    float* __restrict__ out, int out_size) {

    // 33792B buffer: producers overlay As/Bs; consumers overlay lists.
    __shared__ char sbuf[2 * 32 * 132 * 4];
    __shared__ int cnts[2];
    __shared__ float wl[NWARP], wc[NWARP];

    const int t = threadIdx.x;
    const int lane = t & 31;
    const int warp = t >> 5;

    if (blockIdx.x < PROD_B) {
        // =================================================================
        // PRODUCER: gram tile (by, bx); bx==0 blocks also emit row norms.
        // =================================================================
        float (*As)[132] = reinterpret_cast<float(*)[132]>(sbuf);
        float (*Bs)[132] = reinterpret_cast<float(*)[132]>(sbuf + 16896);
        const int by = blockIdx.x / 12;
        const int bx = blockIdx.x % 12;
        const int bi = by * 32;
        const int bj = bx * 32;

        const float4* E4 = reinterpret_cast<const float4*>(E);
        for (int v = t; v < 1024; v += BLK) {
            int r = v >> 5;
            int c4 = v & 31;
            *reinterpret_cast<float4*>(&As[r][c4 * 4]) = E4[(bi + r) * 32 + c4];
            *reinterpret_cast<float4*>(&Bs[r][c4 * 4]) = E4[(bj + r) * 32 + c4];
        }
        __syncthreads();

        if (t < 256) {
            const int ti = t >> 4;
            const int tj = t & 15;
            float acc00 = 0.f, acc01 = 0.f, acc10 = 0.f, acc11 = 0.f;
#pragma unroll 8
            for (int k4 = 0; k4 < 32; k4++) {
                float4 a0 = *reinterpret_cast<const float4*>(&As[ti][k4 * 4]);
                float4 a1 = *reinterpret_cast<const float4*>(&As[ti + 16][k4 * 4]);
                float4 b0 = *reinterpret_cast<const float4*>(&Bs[tj][k4 * 4]);
                float4 b1 = *reinterpret_cast<const float4*>(&Bs[tj + 16][k4 * 4]);
                acc00 = fmaf(a0.x, b0.x, acc00);
                acc00 = fmaf(a0.y, b0.y, acc00);
                acc00 = fmaf(a0.z, b0.z, acc00);
                acc00 = fmaf(a0.w, b0.w, acc00);
                acc01 = fmaf(a0.x, b1.x, acc01);
                acc01 = fmaf(a0.y, b1.y, acc01);
                acc01 = fmaf(a0.z, b1.z, acc01);
                acc01 = fmaf(a0.w, b1.w, acc01);
                acc10 = fmaf(a1.x, b0.x, acc10);
                acc10 = fmaf(a1.y, b0.y, acc10);
                acc10 = fmaf(a1.z, b0.z, acc10);
                acc10 = fmaf(a1.w, b0.w, acc10);
                acc11 = fmaf(a1.x, b1.x, acc11);
                acc11 = fmaf(a1.y, b1.y, acc11);
                acc11 = fmaf(a1.z, b1.z, acc11);
                acc11 = fmaf(a1.w, b1.w, acc11);
            }
            const int gi0 = bi + ti, gi1 = bi + ti + 16;
            const int gj0 = bj + tj, gj1 = bj + tj + 16;
            g_gram[gi0 * N_PTS + gj0] = acc00;
            g_gram[gi0 * N_PTS + gj1] = acc01;
            g_gram[gi1 * N_PTS + gj0] = acc10;
            g_gram[gi1 * N_PTS + gj1] = acc11;
        } else if (bx == 0) {
            // Threads 256..383: row norms from the staged As tile.
            // 4 threads per row, 8 float4 each, width-4 shfl reduce.
            int idx = t - 256;          // 0..127
            int row = idx >> 2;
            int sub = idx & 3;
            float acc = 0.f;
#pragma unroll
            for (int k = 0; k < 8; k++) {
                float4 v = *reinterpret_cast<const float4*>(&As[row][(sub * 8 + k) * 4]);
                acc = fmaf(v.x, v.x, acc);
                acc = fmaf(v.y, v.y, acc);
                acc = fmaf(v.z, v.z, acc);
                acc = fmaf(v.w, v.w, acc);
            }
            acc += __shfl_down_sync(0xFFFFFFFFu, acc, 2, 4);
            acc += __shfl_down_sync(0xFFFFFFFFu, acc, 1, 4);
            if (sub == 0) g_nrm[bi + row] = acc;
        }

        __threadfence();     // publish G (and nrm) before signaling
        __syncthreads();
        if (t == 0) {
            atomicAdd(&g_grp[by], 1u);
            if (bx == 0) atomicAdd(&g_nrmc, 1u);
        }
        return;              // producer exits; SM slot freed
    }

    // =====================================================================
    // CONSUMER: anchors a0..a0+2; spin only on needed row-groups + norms.
    // =====================================================================
    float* spos = reinterpret_cast<float*>(sbuf);
    float* sneg = spos + N_PTS;
    int* slab = reinterpret_cast<int*>(sneg + N_PTS);
    float* snrm = reinterpret_cast<float*>(slab + N_PTS);

    const int cb = blockIdx.x - PROD_B;
    const int a0 = cb * ANCH;

    slab[t] = labels[t];     // overlaps producer execution

    const int grp0 = a0 >> 5;
    const int grp2 = (a0 + ANCH - 1) >> 5;

    if (t == 0) {
        volatile unsigned int* vg = g_grp;
        volatile unsigned int* vn = &g_nrmc;
        while (vg[grp0] < 12u) { }
        while (vg[grp2] < 12u) { }
        while (*vn < 12u) { }
    }
    __syncthreads();
    __threadfence();         // acquire

    // Batched loads: norms + this block's 3 G rows.
    snrm[t] = g_nrm[t];
    float gv[ANCH];
#pragma unroll
    for (int k = 0; k < ANCH; k++) gv[k] = g_gram[(a0 + k) * N_PTS + t];
    const int labt = slab[t];
    int lab_a[ANCH];
#pragma unroll
    for (int k = 0; k < ANCH; k++) lab_a[k] = slab[a0 + k];
    __syncthreads();         // snrm ready

    const float nt = snrm[t];
    const unsigned ltm = (1u << lane) - 1u;
    float loss = 0.f, cnt = 0.f;

#pragma unroll
    for (int k = 0; k < ANCH; k++) {
        if (t < 2) cnts[t] = 0;
        __syncthreads();

        const float dj = snrm[a0 + k] + nt - 2.f * gv[k];   // dist(anchor, t)
        const bool same = (labt == lab_a[k]);

        unsigned ms = __ballot_sync(0xFFFFFFFFu, same);
        unsigned md = ~ms;

        int bp = 0, bn = 0;
        if (lane == 0) {
            bp = atomicAdd(&cnts[0], __popc(ms));
            bn = atomicAdd(&cnts[1], __popc(md));
        }
        bp = __shfl_sync(0xFFFFFFFFu, bp, 0);
        bn = __shfl_sync(0xFFFFFFFFu, bn, 0);

        if (same) spos[bp + __popc(ms & ltm)] = dj;
        else      sneg[bn + __popc(md & ltm)] = dj;
        __syncthreads();

        const int P = cnts[0];
        const int M = cnts[1];
        if (t < M) {
            const float dnm = sneg[t] - MARGIN;
            for (int p = 0; p < P; p++) {
                float L = spos[p] - dnm;
                if (L > 0.f && L < MARGIN) { loss += L; cnt += 1.f; }
            }
        }
        __syncthreads();     // protect list reuse next anchor
    }

    // ---- Reduce + global accumulate + last-ticket writeout ----
#pragma unroll
    for (int off = 16; off > 0; off >>= 1) {
        loss += __shfl_down_sync(0xFFFFFFFFu, loss, off);
        cnt  += __shfl_down_sync(0xFFFFFFFFu, cnt,  off);
    }
    if (lane == 0) { wl[warp] = loss; wc[warp] = cnt; }
    __syncthreads();

    if (t == 0) {
        float l = 0.f, c = 0.f;
#pragma unroll
        for (int w = 0; w < NWARP; w++) { l += wl[w]; c += wc[w]; }
        atomicAdd(&g_acc[0], l);
        atomicAdd(&g_acc[1], c);
        __threadfence();
        unsigned int done = atomicAdd(&g_ticket, 1u);
        if ((done % CONS_B) == CONS_B - 1) {
            __threadfence();
            out[0] = g_acc[0];
            out[1] = g_acc[1];
            for (int k = 2; k < out_size; k++) out[k] = 0.f;
            // Reset flags/accumulators for the next graph replay. Safe: all
            // consumers' spins completed before their tickets arrived.
            g_acc[0] = 0.f;
            g_acc[1] = 0.f;
#pragma unroll
            for (int g = 0; g < 12; g++) g_grp[g] = 0u;
            g_nrmc = 0u;
        }
    }
}

extern "C" void kernel_launch(void* const* d_in, const int* in_sizes, int n_in,
                              void* d_out, int out_size) {
    const float* embeddings = (const float*)d_in[0];
    const int* labels = (const int*)d_in[1];
    float* out = (float*)d_out;

    triplet_one<<<GRID_B, BLK>>>(embeddings, labels, out, out_size);
}